// round 1
// baseline (speedup 1.0000x reference)
#include <cuda_runtime.h>

#define WIN 49
#define HEADS 12
#define HD 32
#define DIMC 384
#define BATCH 4096
#define NWIN 64
#define QKVC (3 * DIMC)   // 1152
#define MROWS (BATCH * WIN) // 200704

// Scratch (allocation-free rule: __device__ globals)
__device__ float g_qkv[(size_t)MROWS * QKVC]; // [B*49, 1152]
__device__ float g_att[(size_t)MROWS * DIMC]; // [B*49, 384]

// ---------------------------------------------------------------------------
// Tiled fp32 GEMM: C[M,N] = A[M,K] @ B[K,N] + bias[N]; first scale_cols of
// each row additionally multiplied by `scale` (folds q * hd^-0.5 into qkv).
// BM=BN=128, BK=8, 256 threads, 8x8 microtile. M%128==0, N%128==0, K%8==0.
// ---------------------------------------------------------------------------
__global__ __launch_bounds__(256) void gemm_bias_kernel(
    const float* __restrict__ A, const float* __restrict__ B,
    const float* __restrict__ bias, float* __restrict__ C,
    int M, int N, int K, int scale_cols, float scale)
{
    constexpr int BM = 128, BN = 128, BK = 8;
    __shared__ float As[BK][BM];
    __shared__ float Bs[BK][BN];

    const int tid = threadIdx.x;
    const int bm = blockIdx.y * BM;
    const int bn = blockIdx.x * BN;
    const int tx = tid & 15;        // 0..15 (cols)
    const int ty = tid >> 4;        // 0..15 (rows)

    // A tile load mapping: 128 rows x 8 k, one float4 per thread
    const int arow = tid >> 1;           // 0..127
    const int acol = (tid & 1) * 4;      // 0 or 4
    // B tile load mapping: 8 k x 128 cols, one float4 per thread
    const int brow = tid >> 5;           // 0..7
    const int bcol = (tid & 31) * 4;     // 0..124

    const float* Aptr = A + (size_t)(bm + arow) * K + acol;
    const float* Bptr = B + (size_t)brow * N + bn + bcol;

    float acc[8][8];
#pragma unroll
    for (int i = 0; i < 8; i++)
#pragma unroll
        for (int j = 0; j < 8; j++) acc[i][j] = 0.f;

    for (int k0 = 0; k0 < K; k0 += BK) {
        float4 av = *(const float4*)(Aptr + k0);
        float4 bv = *(const float4*)(Bptr + (size_t)k0 * N);
        As[acol + 0][arow] = av.x;
        As[acol + 1][arow] = av.y;
        As[acol + 2][arow] = av.z;
        As[acol + 3][arow] = av.w;
        *(float4*)&Bs[brow][bcol] = bv;
        __syncthreads();

#pragma unroll
        for (int kk = 0; kk < BK; kk++) {
            float4 a0 = *(const float4*)&As[kk][ty * 8];
            float4 a1 = *(const float4*)&As[kk][ty * 8 + 4];
            float4 b0 = *(const float4*)&Bs[kk][tx * 8];
            float4 b1 = *(const float4*)&Bs[kk][tx * 8 + 4];
            float ar[8] = {a0.x, a0.y, a0.z, a0.w, a1.x, a1.y, a1.z, a1.w};
            float br[8] = {b0.x, b0.y, b0.z, b0.w, b1.x, b1.y, b1.z, b1.w};
#pragma unroll
            for (int i = 0; i < 8; i++)
#pragma unroll
                for (int j = 0; j < 8; j++)
                    acc[i][j] = fmaf(ar[i], br[j], acc[i][j]);
        }
        __syncthreads();
    }

    // Epilogue: bias + optional scale, float4 stores
    const int col0 = bn + tx * 8;
#pragma unroll
    for (int i = 0; i < 8; i++) {
        const int row = bm + ty * 8 + i;
        float* crow = C + (size_t)row * N + col0;
#pragma unroll
        for (int j4 = 0; j4 < 8; j4 += 4) {
            float4 o;
            float v0 = acc[i][j4 + 0] + bias[col0 + j4 + 0];
            float v1 = acc[i][j4 + 1] + bias[col0 + j4 + 1];
            float v2 = acc[i][j4 + 2] + bias[col0 + j4 + 2];
            float v3 = acc[i][j4 + 3] + bias[col0 + j4 + 3];
            if (col0 + j4 + 0 < scale_cols) v0 *= scale;
            if (col0 + j4 + 1 < scale_cols) v1 *= scale;
            if (col0 + j4 + 2 < scale_cols) v2 *= scale;
            if (col0 + j4 + 3 < scale_cols) v3 *= scale;
            o.x = v0; o.y = v1; o.z = v2; o.w = v3;
            *(float4*)(crow + j4) = o;
        }
    }
}

// ---------------------------------------------------------------------------
// Fused attention per (window b, head h): scores + rel-pos bias + mask,
// softmax, @V. Block = 256 threads (8 warps); each warp owns score rows
// r = warp, warp+8, ... All smem K/V accesses conflict-free via stride-33 pad.
// ---------------------------------------------------------------------------
__global__ __launch_bounds__(256) void attn_kernel(
    const float* __restrict__ qkv,           // [B*49, 1152], q pre-scaled
    const float* __restrict__ mask,          // [64, 49, 49]
    const float* __restrict__ bias_table,    // [169, 12]
    const int*   __restrict__ rel_index,     // [49*49]
    float* __restrict__ out)                 // [B*49, 384]
{
    const int b = blockIdx.x;
    const int h = blockIdx.y;

    __shared__ float qs[WIN][HD + 1];
    __shared__ float ks[WIN][HD + 1];
    __shared__ float vs[WIN][HD + 1];
    __shared__ float bi[WIN][WIN];     // bias + mask combined
    __shared__ float pr[8][WIN];       // per-warp unnormalized probs

    const int tid = threadIdx.x;
    const float* base = qkv + (size_t)b * WIN * QKVC + h * HD;

    for (int idx = tid; idx < WIN * HD; idx += 256) {
        int i = idx >> 5, d = idx & 31;
        qs[i][d] = base[(size_t)i * QKVC + d];
        ks[i][d] = base[(size_t)i * QKVC + DIMC + d];
        vs[i][d] = base[(size_t)i * QKVC + 2 * DIMC + d];
    }
    const float* mrow = mask + (size_t)(b & (NWIN - 1)) * WIN * WIN;
    for (int idx = tid; idx < WIN * WIN; idx += 256) {
        bi[idx / WIN][idx % WIN] = bias_table[rel_index[idx] * HEADS + h] + mrow[idx];
    }
    __syncthreads();

    const int warp = tid >> 5;
    const int lane = tid & 31;

    for (int r = warp; r < WIN; r += 8) {
        // lane handles column j=lane, and j2=lane+32 (valid for lane<17)
        float s0 = 0.f, s1 = 0.f;
        const int j2 = lane + 32;
#pragma unroll
        for (int d = 0; d < HD; d++) {
            float qv = qs[r][d];
            s0 = fmaf(qv, ks[lane][d], s0);
            if (j2 < WIN) s1 = fmaf(qv, ks[j2][d], s1);
        }
        s0 += bi[r][lane];
        s1 = (j2 < WIN) ? (s1 + bi[r][j2]) : -3.0e38f;

        // row max
        float m = fmaxf(s0, s1);
#pragma unroll
        for (int o = 16; o > 0; o >>= 1)
            m = fmaxf(m, __shfl_xor_sync(0xffffffffu, m, o));

        float e0 = __expf(s0 - m);
        float e1 = (j2 < WIN) ? __expf(s1 - m) : 0.f;
        float sum = e0 + e1;
#pragma unroll
        for (int o = 16; o > 0; o >>= 1)
            sum += __shfl_xor_sync(0xffffffffu, sum, o);

        pr[warp][lane] = e0;
        if (j2 < WIN) pr[warp][j2] = e1;
        __syncwarp();

        const float inv = 1.0f / sum;
        float acc = 0.f;
#pragma unroll
        for (int j = 0; j < WIN; j++)
            acc = fmaf(pr[warp][j], vs[j][lane], acc);

        out[((size_t)b * WIN + r) * DIMC + h * HD + lane] = acc * inv;
        __syncwarp();
    }
}

extern "C" void kernel_launch(void* const* d_in, const int* in_sizes, int n_in,
                              void* d_out, int out_size)
{
    const float* x          = (const float*)d_in[0];
    const float* mask       = (const float*)d_in[1];
    const float* qkv_w      = (const float*)d_in[2];
    const float* qkv_b      = (const float*)d_in[3];
    const float* proj_w     = (const float*)d_in[4];
    const float* proj_b     = (const float*)d_in[5];
    const float* bias_table = (const float*)d_in[6];
    const int*   rel_index  = (const int*)d_in[7];
    float* out = (float*)d_out;

    float* qkv; float* att;
    cudaGetSymbolAddress((void**)&qkv, g_qkv);
    cudaGetSymbolAddress((void**)&att, g_att);

    const float qscale = 0.17677669529663687f; // 32^-0.5

    // 1) qkv = x @ qkv_w + qkv_b, q columns scaled
    {
        dim3 grid(QKVC / 128, MROWS / 128);
        gemm_bias_kernel<<<grid, 256>>>(x, qkv_w, qkv_b, qkv,
                                        MROWS, QKVC, DIMC, DIMC, qscale);
    }
    // 2) fused window attention
    {
        dim3 grid(BATCH, HEADS);
        attn_kernel<<<grid, 256>>>(qkv, mask, bias_table, rel_index, att);
    }
    // 3) out = att @ proj_w + proj_b
    {
        dim3 grid(DIMC / 128, MROWS / 128);
        gemm_bias_kernel<<<grid, 256>>>(att, proj_w, proj_b, out,
                                        MROWS, DIMC, DIMC, 0, 1.0f);
    }
}

// round 3
// speedup vs baseline: 1.9043x; 1.9043x over previous
#include <cuda_runtime.h>
#include <cuda_bf16.h>
#include <cstdint>

#define WIN 49
#define HEADS 12
#define HD 32
#define DIMC 384
#define BATCH 4096
#define NWIN 64
#define QKVC (3 * DIMC)     // 1152
#define MROWS (BATCH * WIN) // 200704
#define KTOT 384

// ---------------- scratch (allocation-free rule: __device__ globals) -------
__device__ float g_qkv[(size_t)MROWS * QKVC]; // [B*49, 1152]
__device__ float g_att[(size_t)MROWS * DIMC]; // [B*49, 384]
__device__ __nv_bfloat16 g_wqkv_hi[QKVC * KTOT]; // W^T qkv, [N=1152][K=384]
__device__ __nv_bfloat16 g_wqkv_lo[QKVC * KTOT];
__device__ __nv_bfloat16 g_wprj_hi[DIMC * KTOT]; // W^T proj, [N=384][K=384]
__device__ __nv_bfloat16 g_wprj_lo[DIMC * KTOT];

// ---------------- helpers ---------------------------------------------------
__device__ __forceinline__ uint32_t smem_u32(const void* p) {
    uint32_t a;
    asm("{ .reg .u64 t; cvta.to.shared.u64 t, %1; cvt.u32.u64 %0, t; }" : "=r"(a) : "l"(p));
    return a;
}
__device__ __forceinline__ uint32_t pack2_bf16(float even, float odd) {
    uint32_t r;
    asm("cvt.rn.bf16x2.f32 %0, %1, %2;" : "=r"(r) : "f"(odd), "f"(even));
    return r;
}
__device__ __forceinline__ float lo16f(uint32_t p) { return __uint_as_float(p << 16); }
__device__ __forceinline__ float hi16f(uint32_t p) { return __uint_as_float(p & 0xFFFF0000u); }

__device__ __forceinline__ void ldmx4(uint32_t& r0, uint32_t& r1, uint32_t& r2, uint32_t& r3,
                                      uint32_t addr) {
    asm volatile("ldmatrix.sync.aligned.m8n8.x4.shared.b16 {%0,%1,%2,%3}, [%4];"
                 : "=r"(r0), "=r"(r1), "=r"(r2), "=r"(r3) : "r"(addr));
}
__device__ __forceinline__ void mma16816(float* d, uint32_t a0, uint32_t a1, uint32_t a2,
                                         uint32_t a3, uint32_t b0, uint32_t b1) {
    asm volatile(
        "mma.sync.aligned.m16n8k16.row.col.f32.bf16.bf16.f32 "
        "{%0,%1,%2,%3}, {%4,%5,%6,%7}, {%8,%9}, {%0,%1,%2,%3};"
        : "+f"(d[0]), "+f"(d[1]), "+f"(d[2]), "+f"(d[3])
        : "r"(a0), "r"(a1), "r"(a2), "r"(a3), "r"(b0), "r"(b1));
}
__device__ __forceinline__ void cp_async16(uint32_t saddr, const void* gaddr) {
    asm volatile("cp.async.cg.shared.global [%0], [%1], 16;" :: "r"(saddr), "l"(gaddr) : "memory");
}

// ---------------------------------------------------------------------------
// Weight prep: W [K][N] fp32 -> Wt_hi/Wt_lo [N][K] bf16 (split)
// ---------------------------------------------------------------------------
__global__ void prep_w_kernel(const float* __restrict__ W,
                              __nv_bfloat16* __restrict__ hi,
                              __nv_bfloat16* __restrict__ lo, int K, int N) {
    int idx = blockIdx.x * 256 + threadIdx.x;
    if (idx >= K * N) return;
    int k = idx / N, n = idx % N;
    float f = W[idx];
    __nv_bfloat16 h = __float2bfloat16(f);
    float hf = __bfloat162float(h);
    __nv_bfloat16 l = __float2bfloat16(f - hf);
    hi[(size_t)n * K + k] = h;
    lo[(size_t)n * K + k] = l;
}

// ---------------------------------------------------------------------------
// bf16-split GEMM via mma.sync (HMMA): C[M,Nout] = A[M,384] @ Wt^T + bias
// CTA 128x128, K-chunk 64, 8 warps (warp tile 64x32), 3-term split.
// smem pitch 72 bf16 (144B) -> conflict-free ldmatrix.
// ---------------------------------------------------------------------------
#define BM 128
#define BN 128
#define KC 64
#define NCHUNK (KTOT / KC)  // 6
#define PITCH 72            // bf16 elems per smem row
#define PITCHB 144          // bytes
#define TILEB (128 * PITCHB)      // 18432 bytes per tile buffer
#define AHb 0
#define ALb TILEB
#define BHb (2 * TILEB)
#define BLb (3 * TILEB)
#define GEMM_SMEM (4 * TILEB)     // 73728

__global__ __launch_bounds__(256, 2)
void gemm_tc_kernel(const float* __restrict__ A,
                    const __nv_bfloat16* __restrict__ Bhi,
                    const __nv_bfloat16* __restrict__ Blo,
                    const float* __restrict__ bias, float* __restrict__ C,
                    int Nout, int scale_cols, float scale) {
    extern __shared__ char smem[];
    const uint32_t sb = smem_u32(smem);
    const int tid = threadIdx.x;
    const int warp = tid >> 5, lane = tid & 31;
    const int wm = warp >> 2;       // 0..1  -> rows wm*64
    const int wn = warp & 3;        // 0..3  -> cols wn*32
    const int bm = blockIdx.y * BM, bn = blockIdx.x * BN;

    float acc[4][4][4];
#pragma unroll
    for (int i = 0; i < 4; i++)
#pragma unroll
        for (int j = 0; j < 4; j++)
#pragma unroll
            for (int r = 0; r < 4; r++) acc[i][j][r] = 0.f;

    const float* Abase = A + (size_t)bm * KTOT;

    // per-lane ldmatrix address components
    const int a_r = lane & 15;               // row within 16
    const int a_c = (lane >> 4) * 16;        // byte offset (0 or 16) for k-half
    const int b_lrow = lane & 7;
    const int b_q = lane >> 3;
    const int b_noff = ((b_q >> 1) * 8) + b_lrow;
    const int b_koff = (b_q & 1) * 16;       // bytes

    for (int c = 0; c < NCHUNK; c++) {
        const int k0 = c * KC;
        if (c) __syncthreads();   // all warps done reading previous tile

        // --- B tiles via cp.async (pre-split bf16, [N][K] row-major) ---
#pragma unroll
        for (int i = 0; i < 8; i++) {
            int g = tid + 256 * i;           // 0..2047
            int t = (g >= 1024);
            int r = g & 1023;
            int row = r >> 3, k8 = r & 7;
            const __nv_bfloat16* src =
                (t ? Blo : Bhi) + ((size_t)(bn + row) * KTOT + k0 + k8 * 8);
            cp_async16(sb + (t ? BLb : BHb) + row * PITCHB + k8 * 16, src);
        }
        asm volatile("cp.async.commit_group;" ::: "memory");

        // --- A tile: fp32 -> bf16 hi/lo split ---
#pragma unroll
        for (int i = 0; i < 8; i++) {
            int g = tid + 256 * i;           // 0..2047
            int row = g >> 4, k4 = g & 15;   // 4 floats per granule
            float4 f = *(const float4*)(Abase + (size_t)row * KTOT + k0 + k4 * 4);
            uint32_t h0 = pack2_bf16(f.x, f.y), h1 = pack2_bf16(f.z, f.w);
            uint32_t l0 = pack2_bf16(f.x - lo16f(h0), f.y - hi16f(h0));
            uint32_t l1 = pack2_bf16(f.z - lo16f(h1), f.w - hi16f(h1));
            uint32_t off = row * PITCHB + k4 * 8;
            asm volatile("st.shared.v2.b32 [%0], {%1,%2};"
                         :: "r"(sb + AHb + off), "r"(h0), "r"(h1) : "memory");
            asm volatile("st.shared.v2.b32 [%0], {%1,%2};"
                         :: "r"(sb + ALb + off), "r"(l0), "r"(l1) : "memory");
        }
        asm volatile("cp.async.wait_group 0;" ::: "memory");
        __syncthreads();

        // --- compute: 4 k16 steps ---
#pragma unroll
        for (int kk = 0; kk < 4; kk++) {
            const uint32_t kbyte = kk * 32;
            uint32_t Ah[4][4], Al[4][4], Bh[2][4], Bl[2][4];
#pragma unroll
            for (int mt = 0; mt < 4; mt++) {
                uint32_t ad = sb + (wm * 64 + mt * 16 + a_r) * PITCHB + kbyte + a_c;
                ldmx4(Ah[mt][0], Ah[mt][1], Ah[mt][2], Ah[mt][3], ad + AHb);
                ldmx4(Al[mt][0], Al[mt][1], Al[mt][2], Al[mt][3], ad + ALb);
            }
#pragma unroll
            for (int p = 0; p < 2; p++) {
                uint32_t bd = sb + (wn * 32 + p * 16 + b_noff) * PITCHB + kbyte + b_koff;
                ldmx4(Bh[p][0], Bh[p][1], Bh[p][2], Bh[p][3], bd + BHb);
                ldmx4(Bl[p][0], Bl[p][1], Bl[p][2], Bl[p][3], bd + BLb);
            }
#pragma unroll
            for (int mt = 0; mt < 4; mt++)
#pragma unroll
                for (int nt = 0; nt < 4; nt++) {
                    const int p = nt >> 1, h = (nt & 1) * 2;
                    mma16816(acc[mt][nt], Ah[mt][0], Ah[mt][1], Ah[mt][2], Ah[mt][3],
                             Bh[p][h], Bh[p][h + 1]);
                    mma16816(acc[mt][nt], Ah[mt][0], Ah[mt][1], Ah[mt][2], Ah[mt][3],
                             Bl[p][h], Bl[p][h + 1]);
                    mma16816(acc[mt][nt], Al[mt][0], Al[mt][1], Al[mt][2], Al[mt][3],
                             Bh[p][h], Bh[p][h + 1]);
                }
        }
    }

    // --- epilogue ---
    const int gid = lane >> 2, tig = lane & 3;
#pragma unroll
    for (int mt = 0; mt < 4; mt++) {
        const int row = bm + wm * 64 + mt * 16 + gid;
#pragma unroll
        for (int nt = 0; nt < 4; nt++) {
            const int col = bn + wn * 32 + nt * 8 + tig * 2;
            const float b0 = bias[col], b1 = bias[col + 1];
            const float s = (col < scale_cols) ? scale : 1.0f;
            float2 v0 = make_float2((acc[mt][nt][0] + b0) * s, (acc[mt][nt][1] + b1) * s);
            float2 v1 = make_float2((acc[mt][nt][2] + b0) * s, (acc[mt][nt][3] + b1) * s);
            *(float2*)(C + (size_t)row * Nout + col) = v0;
            *(float2*)(C + (size_t)(row + 8) * Nout + col) = v1;
        }
    }
}

// ---------------------------------------------------------------------------
// Fused attention per (window b, head h) — unchanged from passing round 1
// ---------------------------------------------------------------------------
__global__ __launch_bounds__(256) void attn_kernel(
    const float* __restrict__ qkv, const float* __restrict__ mask,
    const float* __restrict__ bias_table, const int* __restrict__ rel_index,
    float* __restrict__ out) {
    const int b = blockIdx.x;
    const int h = blockIdx.y;

    __shared__ float qs[WIN][HD + 1];
    __shared__ float ks[WIN][HD + 1];
    __shared__ float vs[WIN][HD + 1];
    __shared__ float bi[WIN][WIN];
    __shared__ float pr[8][WIN];

    const int tid = threadIdx.x;
    const float* base = qkv + (size_t)b * WIN * QKVC + h * HD;

    for (int idx = tid; idx < WIN * HD; idx += 256) {
        int i = idx >> 5, d = idx & 31;
        qs[i][d] = base[(size_t)i * QKVC + d];
        ks[i][d] = base[(size_t)i * QKVC + DIMC + d];
        vs[i][d] = base[(size_t)i * QKVC + 2 * DIMC + d];
    }
    const float* mrow = mask + (size_t)(b & (NWIN - 1)) * WIN * WIN;
    for (int idx = tid; idx < WIN * WIN; idx += 256) {
        bi[idx / WIN][idx % WIN] = bias_table[rel_index[idx] * HEADS + h] + mrow[idx];
    }
    __syncthreads();

    const int warp = tid >> 5;
    const int lane = tid & 31;

    for (int r = warp; r < WIN; r += 8) {
        float s0 = 0.f, s1 = 0.f;
        const int j2 = lane + 32;
#pragma unroll
        for (int d = 0; d < HD; d++) {
            float qv = qs[r][d];
            s0 = fmaf(qv, ks[lane][d], s0);
            if (j2 < WIN) s1 = fmaf(qv, ks[j2][d], s1);
        }
        s0 += bi[r][lane];
        s1 = (j2 < WIN) ? (s1 + bi[r][j2]) : -3.0e38f;

        float m = fmaxf(s0, s1);
#pragma unroll
        for (int o = 16; o > 0; o >>= 1)
            m = fmaxf(m, __shfl_xor_sync(0xffffffffu, m, o));

        float e0 = __expf(s0 - m);
        float e1 = (j2 < WIN) ? __expf(s1 - m) : 0.f;
        float sum = e0 + e1;
#pragma unroll
        for (int o = 16; o > 0; o >>= 1)
            sum += __shfl_xor_sync(0xffffffffu, sum, o);

        pr[warp][lane] = e0;
        if (j2 < WIN) pr[warp][j2] = e1;
        __syncwarp();

        const float inv = 1.0f / sum;
        float acc = 0.f;
#pragma unroll
        for (int j = 0; j < WIN; j++)
            acc = fmaf(pr[warp][j], vs[j][lane], acc);

        out[((size_t)b * WIN + r) * DIMC + h * HD + lane] = acc * inv;
        __syncwarp();
    }
}

// ---------------------------------------------------------------------------
extern "C" void kernel_launch(void* const* d_in, const int* in_sizes, int n_in,
                              void* d_out, int out_size) {
    const float* x          = (const float*)d_in[0];
    const float* mask       = (const float*)d_in[1];
    const float* qkv_w      = (const float*)d_in[2];
    const float* qkv_b      = (const float*)d_in[3];
    const float* proj_w     = (const float*)d_in[4];
    const float* proj_b     = (const float*)d_in[5];
    const float* bias_table = (const float*)d_in[6];
    const int*   rel_index  = (const int*)d_in[7];
    float* out = (float*)d_out;

    float *qkv, *att;
    __nv_bfloat16 *wq_hi, *wq_lo, *wp_hi, *wp_lo;
    cudaGetSymbolAddress((void**)&qkv, g_qkv);
    cudaGetSymbolAddress((void**)&att, g_att);
    cudaGetSymbolAddress((void**)&wq_hi, g_wqkv_hi);
    cudaGetSymbolAddress((void**)&wq_lo, g_wqkv_lo);
    cudaGetSymbolAddress((void**)&wp_hi, g_wprj_hi);
    cudaGetSymbolAddress((void**)&wp_lo, g_wprj_lo);

    cudaFuncSetAttribute(gemm_tc_kernel, cudaFuncAttributeMaxDynamicSharedMemorySize, GEMM_SMEM);

    const float qscale = 0.17677669529663687f; // 32^-0.5

    // 0) weight transpose + bf16 split
    prep_w_kernel<<<(KTOT * QKVC + 255) / 256, 256>>>(qkv_w, wq_hi, wq_lo, KTOT, QKVC);
    prep_w_kernel<<<(KTOT * DIMC + 255) / 256, 256>>>(proj_w, wp_hi, wp_lo, KTOT, DIMC);

    // 1) qkv = x @ qkv_w + qkv_b (q columns scaled)
    {
        dim3 grid(QKVC / BN, MROWS / BM);
        gemm_tc_kernel<<<grid, 256, GEMM_SMEM>>>(x, wq_hi, wq_lo, qkv_b, qkv,
                                                 QKVC, DIMC, qscale);
    }
    // 2) fused window attention
    {
        dim3 grid(BATCH, HEADS);
        attn_kernel<<<grid, 256>>>(qkv, mask, bias_table, rel_index, att);
    }
    // 3) out = att @ proj_w + proj_b
    {
        dim3 grid(DIMC / BN, MROWS / BM);
        gemm_tc_kernel<<<grid, 256, GEMM_SMEM>>>(att, wp_hi, wp_lo, proj_b, out,
                                                 DIMC, 0, 1.0f);
    }
}

// round 4
// speedup vs baseline: 2.1762x; 1.1428x over previous
#include <cuda_runtime.h>
#include <cuda_fp16.h>
#include <cstdint>

#define WIN 49
#define HEADS 12
#define HD 32
#define DIMC 384
#define BATCH 4096
#define NWIN 64
#define QKVC (3 * DIMC)     // 1152
#define MROWS (BATCH * WIN) // 200704
#define KTOT 384

// ---------------- scratch (allocation-free rule: __device__ globals) -------
__device__ float g_qkv[(size_t)MROWS * QKVC]; // [B*49, 1152]
__device__ float g_att[(size_t)MROWS * DIMC]; // [B*49, 384]
__device__ __half g_wqkv_hi[QKVC * KTOT]; // W^T qkv, [N=1152][K=384]
__device__ __half g_wqkv_lo[QKVC * KTOT];
__device__ __half g_wprj_hi[DIMC * KTOT]; // W^T proj, [N=384][K=384]
__device__ __half g_wprj_lo[DIMC * KTOT];

// ---------------- helpers ---------------------------------------------------
__device__ __forceinline__ uint32_t smem_u32(const void* p) {
    uint32_t a;
    asm("{ .reg .u64 t; cvta.to.shared.u64 t, %1; cvt.u32.u64 %0, t; }" : "=r"(a) : "l"(p));
    return a;
}
// pack two fp32 -> fp16x2 (lo = even, hi = odd)
__device__ __forceinline__ uint32_t pack2_f16(float even, float odd) {
    uint32_t r;
    asm("cvt.rn.f16x2.f32 %0, %1, %2;" : "=r"(r) : "f"(odd), "f"(even));
    return r;
}

__device__ __forceinline__ void ldmx4(uint32_t& r0, uint32_t& r1, uint32_t& r2, uint32_t& r3,
                                      uint32_t addr) {
    asm volatile("ldmatrix.sync.aligned.m8n8.x4.shared.b16 {%0,%1,%2,%3}, [%4];"
                 : "=r"(r0), "=r"(r1), "=r"(r2), "=r"(r3) : "r"(addr));
}
__device__ __forceinline__ void mma16816(float* d, uint32_t a0, uint32_t a1, uint32_t a2,
                                         uint32_t a3, uint32_t b0, uint32_t b1) {
    asm volatile(
        "mma.sync.aligned.m16n8k16.row.col.f32.f16.f16.f32 "
        "{%0,%1,%2,%3}, {%4,%5,%6,%7}, {%8,%9}, {%0,%1,%2,%3};"
        : "+f"(d[0]), "+f"(d[1]), "+f"(d[2]), "+f"(d[3])
        : "r"(a0), "r"(a1), "r"(a2), "r"(a3), "r"(b0), "r"(b1));
}
__device__ __forceinline__ void cp_async16(uint32_t saddr, const void* gaddr) {
    asm volatile("cp.async.cg.shared.global [%0], [%1], 16;" :: "r"(saddr), "l"(gaddr) : "memory");
}

// ---------------------------------------------------------------------------
// Weight prep: W [K][N] fp32 -> Wt_hi/Wt_lo [N][K] fp16 (hi + residual lo)
// ---------------------------------------------------------------------------
__global__ void prep_w_kernel(const float* __restrict__ W,
                              __half* __restrict__ hi,
                              __half* __restrict__ lo, int K, int N) {
    int idx = blockIdx.x * 256 + threadIdx.x;
    if (idx >= K * N) return;
    int k = idx / N, n = idx % N;
    float f = W[idx];
    __half h = __float2half_rn(f);
    float hf = __half2float(h);
    __half l = __float2half_rn(f - hf);
    hi[(size_t)n * K + k] = h;
    lo[(size_t)n * K + k] = l;
}

// ---------------------------------------------------------------------------
// 2-term fp16 GEMM via mma.sync: C = round_f16(A) @ (Wh + Wl)^T + bias
// CTA 128x128, K-chunk 64, 8 warps (warp tile 64x32).
// smem pitch 72 fp16 (144B) -> conflict-free ldmatrix.
// ---------------------------------------------------------------------------
#define BM 128
#define BN 128
#define KC 64
#define NCHUNK (KTOT / KC)  // 6
#define PITCHB 144          // bytes per smem row
#define TILEB (128 * PITCHB)      // 18432 bytes per tile buffer
#define Ab  0
#define BHb TILEB
#define BLb (2 * TILEB)
#define GEMM_SMEM (3 * TILEB)     // 55296

__global__ __launch_bounds__(256, 2)
void gemm_tc_kernel(const float* __restrict__ A,
                    const __half* __restrict__ Bhi,
                    const __half* __restrict__ Blo,
                    const float* __restrict__ bias, float* __restrict__ C,
                    int Nout, int scale_cols, float scale) {
    extern __shared__ char smem[];
    const uint32_t sb = smem_u32(smem);
    const int tid = threadIdx.x;
    const int warp = tid >> 5, lane = tid & 31;
    const int wm = warp >> 2;       // 0..1  -> rows wm*64
    const int wn = warp & 3;        // 0..3  -> cols wn*32
    const int bm = blockIdx.y * BM, bn = blockIdx.x * BN;

    float acc[4][4][4];
#pragma unroll
    for (int i = 0; i < 4; i++)
#pragma unroll
        for (int j = 0; j < 4; j++)
#pragma unroll
            for (int r = 0; r < 4; r++) acc[i][j][r] = 0.f;

    const float* Abase = A + (size_t)bm * KTOT;

    // per-lane ldmatrix address components
    const int a_r = lane & 15;               // row within 16
    const int a_c = (lane >> 4) * 16;        // byte offset (0/16) for k-half
    const int b_lrow = lane & 7;
    const int b_q = lane >> 3;
    const int b_noff = ((b_q >> 1) * 8) + b_lrow;
    const int b_koff = (b_q & 1) * 16;       // bytes

    for (int c = 0; c < NCHUNK; c++) {
        const int k0 = c * KC;
        if (c) __syncthreads();   // all warps done reading previous tile

        // --- W tiles via cp.async (pre-split fp16, [N][K] row-major) ---
#pragma unroll
        for (int i = 0; i < 8; i++) {
            int g = tid + 256 * i;           // 0..2047
            int t = (g >= 1024);
            int r = g & 1023;
            int row = r >> 3, k8 = r & 7;
            const __half* src =
                (t ? Blo : Bhi) + ((size_t)(bn + row) * KTOT + k0 + k8 * 8);
            cp_async16(sb + (t ? BLb : BHb) + row * PITCHB + k8 * 16, src);
        }
        asm volatile("cp.async.commit_group;" ::: "memory");

        // --- A tile: fp32 -> fp16 round ---
#pragma unroll
        for (int i = 0; i < 8; i++) {
            int g = tid + 256 * i;           // 0..2047
            int row = g >> 4, k4 = g & 15;   // 4 floats per granule
            float4 f = *(const float4*)(Abase + (size_t)row * KTOT + k0 + k4 * 4);
            uint32_t h0 = pack2_f16(f.x, f.y), h1 = pack2_f16(f.z, f.w);
            asm volatile("st.shared.v2.b32 [%0], {%1,%2};"
                         :: "r"(sb + Ab + row * PITCHB + k4 * 8), "r"(h0), "r"(h1) : "memory");
        }
        asm volatile("cp.async.wait_group 0;" ::: "memory");
        __syncthreads();

        // --- compute: 4 k16 steps, 2 MMA terms (A·Wh + A·Wl) ---
#pragma unroll
        for (int kk = 0; kk < 4; kk++) {
            const uint32_t kbyte = kk * 32;
            uint32_t Ar[4][4], Bh[2][4], Bl[2][4];
#pragma unroll
            for (int mt = 0; mt < 4; mt++) {
                uint32_t ad = sb + Ab + (wm * 64 + mt * 16 + a_r) * PITCHB + kbyte + a_c;
                ldmx4(Ar[mt][0], Ar[mt][1], Ar[mt][2], Ar[mt][3], ad);
            }
#pragma unroll
            for (int p = 0; p < 2; p++) {
                uint32_t bd = sb + (wn * 32 + p * 16 + b_noff) * PITCHB + kbyte + b_koff;
                ldmx4(Bh[p][0], Bh[p][1], Bh[p][2], Bh[p][3], bd + BHb);
                ldmx4(Bl[p][0], Bl[p][1], Bl[p][2], Bl[p][3], bd + BLb);
            }
#pragma unroll
            for (int mt = 0; mt < 4; mt++)
#pragma unroll
                for (int nt = 0; nt < 4; nt++) {
                    const int p = nt >> 1, h = (nt & 1) * 2;
                    mma16816(acc[mt][nt], Ar[mt][0], Ar[mt][1], Ar[mt][2], Ar[mt][3],
                             Bh[p][h], Bh[p][h + 1]);
                    mma16816(acc[mt][nt], Ar[mt][0], Ar[mt][1], Ar[mt][2], Ar[mt][3],
                             Bl[p][h], Bl[p][h + 1]);
                }
        }
    }

    // --- epilogue ---
    const int gid = lane >> 2, tig = lane & 3;
#pragma unroll
    for (int mt = 0; mt < 4; mt++) {
        const int row = bm + wm * 64 + mt * 16 + gid;
#pragma unroll
        for (int nt = 0; nt < 4; nt++) {
            const int col = bn + wn * 32 + nt * 8 + tig * 2;
            const float b0 = bias[col], b1 = bias[col + 1];
            const float s = (col < scale_cols) ? scale : 1.0f;
            float2 v0 = make_float2((acc[mt][nt][0] + b0) * s, (acc[mt][nt][1] + b1) * s);
            float2 v1 = make_float2((acc[mt][nt][2] + b0) * s, (acc[mt][nt][3] + b1) * s);
            *(float2*)(C + (size_t)row * Nout + col) = v0;
            *(float2*)(C + (size_t)(row + 8) * Nout + col) = v1;
        }
    }
}

// ---------------------------------------------------------------------------
// Fused attention per (window b, head h) — unchanged (fp32)
// ---------------------------------------------------------------------------
__global__ __launch_bounds__(256) void attn_kernel(
    const float* __restrict__ qkv, const float* __restrict__ mask,
    const float* __restrict__ bias_table, const int* __restrict__ rel_index,
    float* __restrict__ out) {
    const int b = blockIdx.x;
    const int h = blockIdx.y;

    __shared__ float qs[WIN][HD + 1];
    __shared__ float ks[WIN][HD + 1];
    __shared__ float vs[WIN][HD + 1];
    __shared__ float bi[WIN][WIN];
    __shared__ float pr[8][WIN];

    const int tid = threadIdx.x;
    const float* base = qkv + (size_t)b * WIN * QKVC + h * HD;

    for (int idx = tid; idx < WIN * HD; idx += 256) {
        int i = idx >> 5, d = idx & 31;
        qs[i][d] = base[(size_t)i * QKVC + d];
        ks[i][d] = base[(size_t)i * QKVC + DIMC + d];
        vs[i][d] = base[(size_t)i * QKVC + 2 * DIMC + d];
    }
    const float* mrow = mask + (size_t)(b & (NWIN - 1)) * WIN * WIN;
    for (int idx = tid; idx < WIN * WIN; idx += 256) {
        bi[idx / WIN][idx % WIN] = bias_table[rel_index[idx] * HEADS + h] + mrow[idx];
    }
    __syncthreads();

    const int warp = tid >> 5;
    const int lane = tid & 31;

    for (int r = warp; r < WIN; r += 8) {
        float s0 = 0.f, s1 = 0.f;
        const int j2 = lane + 32;
#pragma unroll
        for (int d = 0; d < HD; d++) {
            float qv = qs[r][d];
            s0 = fmaf(qv, ks[lane][d], s0);
            if (j2 < WIN) s1 = fmaf(qv, ks[j2][d], s1);
        }
        s0 += bi[r][lane];
        s1 = (j2 < WIN) ? (s1 + bi[r][j2]) : -3.0e38f;

        float m = fmaxf(s0, s1);
#pragma unroll
        for (int o = 16; o > 0; o >>= 1)
            m = fmaxf(m, __shfl_xor_sync(0xffffffffu, m, o));

        float e0 = __expf(s0 - m);
        float e1 = (j2 < WIN) ? __expf(s1 - m) : 0.f;
        float sum = e0 + e1;
#pragma unroll
        for (int o = 16; o > 0; o >>= 1)
            sum += __shfl_xor_sync(0xffffffffu, sum, o);

        pr[warp][lane] = e0;
        if (j2 < WIN) pr[warp][j2] = e1;
        __syncwarp();

        const float inv = 1.0f / sum;
        float acc = 0.f;
#pragma unroll
        for (int j = 0; j < WIN; j++)
            acc = fmaf(pr[warp][j], vs[j][lane], acc);

        out[((size_t)b * WIN + r) * DIMC + h * HD + lane] = acc * inv;
        __syncwarp();
    }
}

// ---------------------------------------------------------------------------
extern "C" void kernel_launch(void* const* d_in, const int* in_sizes, int n_in,
                              void* d_out, int out_size) {
    const float* x          = (const float*)d_in[0];
    const float* mask       = (const float*)d_in[1];
    const float* qkv_w      = (const float*)d_in[2];
    const float* qkv_b      = (const float*)d_in[3];
    const float* proj_w     = (const float*)d_in[4];
    const float* proj_b     = (const float*)d_in[5];
    const float* bias_table = (const float*)d_in[6];
    const int*   rel_index  = (const int*)d_in[7];
    float* out = (float*)d_out;

    float *qkv, *att;
    __half *wq_hi, *wq_lo, *wp_hi, *wp_lo;
    cudaGetSymbolAddress((void**)&qkv, g_qkv);
    cudaGetSymbolAddress((void**)&att, g_att);
    cudaGetSymbolAddress((void**)&wq_hi, g_wqkv_hi);
    cudaGetSymbolAddress((void**)&wq_lo, g_wqkv_lo);
    cudaGetSymbolAddress((void**)&wp_hi, g_wprj_hi);
    cudaGetSymbolAddress((void**)&wp_lo, g_wprj_lo);

    cudaFuncSetAttribute(gemm_tc_kernel, cudaFuncAttributeMaxDynamicSharedMemorySize, GEMM_SMEM);

    const float qscale = 0.17677669529663687f; // 32^-0.5

    // 0) weight transpose + fp16 hi/lo split
    prep_w_kernel<<<(KTOT * QKVC + 255) / 256, 256>>>(qkv_w, wq_hi, wq_lo, KTOT, QKVC);
    prep_w_kernel<<<(KTOT * DIMC + 255) / 256, 256>>>(proj_w, wp_hi, wp_lo, KTOT, DIMC);

    // 1) qkv = x @ qkv_w + qkv_b (q columns scaled)
    {
        dim3 grid(QKVC / BN, MROWS / BM);
        gemm_tc_kernel<<<grid, 256, GEMM_SMEM>>>(x, wq_hi, wq_lo, qkv_b, qkv,
                                                 QKVC, DIMC, qscale);
    }
    // 2) fused window attention
    {
        dim3 grid(BATCH, HEADS);
        attn_kernel<<<grid, 256>>>(qkv, mask, bias_table, rel_index, att);
    }
    // 3) out = att @ proj_w + proj_b
    {
        dim3 grid(DIMC / BN, MROWS / BM);
        gemm_tc_kernel<<<grid, 256, GEMM_SMEM>>>(att, wp_hi, wp_lo, proj_b, out,
                                                 DIMC, 0, 1.0f);
    }
}